// round 16
// baseline (speedup 1.0000x reference)
#include <cuda_runtime.h>
#include <cuda_fp16.h>
#include <cstdint>

// Problem constants (fixed-shape problem)
#define NN      50000
#define EE_MAX  800000
#define GG      128
#define DINF    200
#define DHF     128
#define NLAY    4
#define BN_EPS  1e-5f
#define OUTW    (DINF + NLAY * DHF)   // 712
#define WPAIRS  548
#define APK_W   50
#define NTILES  ((NN + 63) / 64)      // 782
#define BNP_CH  16                    // rows per pooling chunk
#define NCHUNK  (NN / BNP_CH)         // 3125 exact

// ---------------- scratch (device globals; no allocation allowed) ----------
__device__ uint4    g_apk    [NN * APK_W];
__device__ float    g_mid    [NN * DHF];
__device__ float    g_rep    [NN * DHF];
__device__ int      g_cnt    [2 * NN];
__device__ int      g_rowptr [NN + 1];
__device__ int      g_colidx [EE_MAX];
__device__ float    g_sum    [2 * NLAY][DHF];
__device__ float    g_sumsq  [2 * NLAY][DHF];
__device__ uint32_t g_wpk    [WPAIRS * DHF];       // fp16x2 of W pair-rows
__device__ unsigned g_bar_cnt;
__device__ unsigned g_bar_gen;

// ---------------- device-wide barrier (all blocks resident) ----------------
__device__ __forceinline__ void grid_sync() {
    __syncthreads();
    if (threadIdx.x == 0) {
        unsigned gen = *(volatile unsigned*)&g_bar_gen;
        __threadfence();
        unsigned ticket = atomicAdd(&g_bar_cnt, 1u);
        if (ticket == gridDim.x - 1) {
            g_bar_cnt = 0u;
            __threadfence();
            atomicAdd(&g_bar_gen, 1u);
        } else {
            while (*(volatile unsigned*)&g_bar_gen == gen) __nanosleep(64);
        }
        __threadfence();
    }
    __syncthreads();
}

// ---------------- fp16 hi/lo split helpers ---------------------------------
__device__ __forceinline__ uint32_t pack_f16(float v0, float v1, float& rem0, float& rem1) {
    __half h0 = __float2half_rn(v0);
    __half h1 = __float2half_rn(v1);
    rem0 = v0 - __half2float(h0);
    rem1 = v1 - __half2float(h1);
    return ((uint32_t)__half_as_ushort(h1) << 16) | (uint32_t)__half_as_ushort(h0);
}
__device__ __forceinline__ uint32_t pack_f16_rn(float v0, float v1) {
    __half2 p = __floats2half2_rn(v0, v1);   // .x = v0 (low half)
    return *(uint32_t*)&p;
}

// -------- weight prepack (fp16) + hist zero + out zero ---------------------
__global__ void k_packw(const float* __restrict__ w1_0, const float* __restrict__ w2_0,
                        const float* __restrict__ w1_r, const float* __restrict__ w2_r,
                        float* __restrict__ out, int out_n) {
    int b = blockIdx.x;
    int c = threadIdx.x;
    int gtid = b * DHF + c;
    for (int i = gtid; i < NN; i += WPAIRS * DHF) g_cnt[i] = 0;
    for (int i = gtid; i < out_n; i += WPAIRS * DHF) out[i] = 0.f;

    const float* src;
    int kp;
    if (b < 100)      { src = w1_0; kp = b; }
    else if (b < 164) { src = w2_0; kp = b - 100; }
    else {
        int r = b - 164;
        if (r < 192) { src = w1_r + (r / 64) * DHF * DHF; kp = r % 64; }
        else { r -= 192; src = w2_r + (r / 64) * DHF * DHF; kp = r % 64; }
    }
    float v0 = src[(size_t)(2 * kp) * DHF + c];
    float v1 = src[(size_t)(2 * kp + 1) * DHF + c];
    g_wpk[b * DHF + c] = pack_f16_rn(v0, v1);
}

// ---------------- CSR build ------------------------------------------------
__global__ void k_hist(const int* __restrict__ erow, int E) {
    int e = blockIdx.x * blockDim.x + threadIdx.x;
    if (e < E) atomicAdd(&g_cnt[erow[e]], 1);
}

__global__ void k_scan_big() {
    extern __shared__ int sc[];
    int* part = sc + NN;
    const int T = 1024;
    int t = threadIdx.x;

    if (t < DHF) {
        for (int l = 0; l < 2 * NLAY; l++) { g_sum[l][t] = 0.f; g_sumsq[l][t] = 0.f; }
    }
    for (int i = t; i < NN; i += T) {
        sc[i] = g_cnt[i];
        g_cnt[NN + i] = 0;
    }
    __syncthreads();

    const int C = (NN + T - 1) / T;
    int base = t * C;
    int s = 0;
    for (int j = 0; j < C; j++) {
        int i = base + j;
        if (i < NN) s += sc[i];
    }
    part[t] = s;
    __syncthreads();
    for (int off = 1; off < T; off <<= 1) {
        int v = (t >= off) ? part[t - off] : 0;
        __syncthreads();
        part[t] += v;
        __syncthreads();
    }
    int pre = (t > 0) ? part[t - 1] : 0;
    for (int j = 0; j < C; j++) {
        int i = base + j;
        if (i < NN) {
            int c = sc[i];
            sc[i] = pre;
            pre += c;
        }
    }
    __syncthreads();
    for (int i = t; i < NN; i += T) g_rowptr[i] = sc[i];
    if (t == T - 1) g_rowptr[NN] = pre;
}

__global__ void k_scatter(const int* __restrict__ erow, const int* __restrict__ ecol, int E) {
    int e = blockIdx.x * blockDim.x + threadIdx.x;
    if (e < E) {
        int r = erow[e];
        int p = g_rowptr[r] + atomicAdd(&g_cnt[NN + r], 1);
        g_colidx[p] = ecol[e];
    }
}

// ---------------- fused layer kernel phases ---------------------------------
__device__ __forceinline__ void mma16(float* c, const uint32_t* a, const uint32_t* b) {
    asm volatile(
        "mma.sync.aligned.m16n8k16.row.col.f32.f16.f16.f32 "
        "{%0,%1,%2,%3}, {%4,%5,%6,%7}, {%8,%9}, {%0,%1,%2,%3};"
        : "+f"(c[0]), "+f"(c[1]), "+f"(c[2]), "+f"(c[3])
        : "r"(a[0]), "r"(a[1]), "r"(a[2]), "r"(a[3]), "r"(b[0]), "r"(b[1]));
}

struct GemmSmem {
    uint32_t ash[2][8][72], asl[2][8][72];
    uint32_t wsh[2][8][136];
    float strs[DHF], strh[DHF];
};

// layer-0 spmm over raw x (warp per node, strided); emits packed hi/lo fp16 A
__device__ void spmm_x_phase(const float* __restrict__ hin, uint4* __restrict__ pout,
                             float se) {
    const int D4 = DINF / 4;   // 50
    const int S = 2;
    int lane = threadIdx.x & 31;
    int wstride = gridDim.x * 8;
    for (int wid = blockIdx.x * 8 + (threadIdx.x >> 5); wid < NN; wid += wstride) {
        const float4* selfr = (const float4*)hin + (size_t)wid * D4;
        float4 acc[S];
#pragma unroll
        for (int s = 0; s < S; s++) {
            int j = lane + 32 * s;
            if (j < D4) {
                float4 v = selfr[j];
                acc[s] = make_float4(v.x * se, v.y * se, v.z * se, v.w * se);
            } else acc[s] = make_float4(0.f, 0.f, 0.f, 0.f);
        }
        int e0 = g_rowptr[wid], e1 = g_rowptr[wid + 1];
        int e = e0;
        for (; e + 4 <= e1; e += 4) {
            const float4* r0 = (const float4*)hin + (size_t)g_colidx[e] * D4;
            const float4* r1 = (const float4*)hin + (size_t)g_colidx[e + 1] * D4;
            const float4* r2 = (const float4*)hin + (size_t)g_colidx[e + 2] * D4;
            const float4* r3 = (const float4*)hin + (size_t)g_colidx[e + 3] * D4;
#pragma unroll
            for (int s = 0; s < S; s++) {
                int j = lane + 32 * s;
                if (j < D4) {
                    float4 v0 = r0[j], v1 = r1[j], v2 = r2[j], v3 = r3[j];
                    acc[s].x += (v0.x + v1.x) + (v2.x + v3.x);
                    acc[s].y += (v0.y + v1.y) + (v2.y + v3.y);
                    acc[s].z += (v0.z + v1.z) + (v2.z + v3.z);
                    acc[s].w += (v0.w + v1.w) + (v2.w + v3.w);
                }
            }
        }
        for (; e < e1; e++) {
            const float4* r = (const float4*)hin + (size_t)g_colidx[e] * D4;
#pragma unroll
            for (int s = 0; s < S; s++) {
                int j = lane + 32 * s;
                if (j < D4) {
                    float4 v = r[j];
                    acc[s].x += v.x; acc[s].y += v.y; acc[s].z += v.z; acc[s].w += v.w;
                }
            }
        }
        uint4* o = pout + (size_t)wid * D4;
#pragma unroll
        for (int s = 0; s < S; s++) {
            int j = lane + 32 * s;
            if (j < D4) {
                float r0, r1, r2, r3;
                uint32_t h01 = pack_f16(acc[s].x, acc[s].y, r0, r1);
                uint32_t h23 = pack_f16(acc[s].z, acc[s].w, r2, r3);
                o[j] = make_uint4(h01, h23, pack_f16_rn(r0, r1), pack_f16_rn(r2, r3));
            }
        }
    }
}

// layers 1..3 spmm: reads raw rep, applies BN+ReLU per element on the fly,
// pools self h-values (= prev layer's pooled output), warp per 16-node chunk.
__device__ void spmm_bnpool_phase(const float* __restrict__ rep, uint4* __restrict__ pout,
                                  float se, int slot,
                                  const float* __restrict__ gamma,
                                  const float* __restrict__ beta,
                                  const int* __restrict__ gids,
                                  float* __restrict__ out, int offprev) {
    const int D4 = DHF / 4;   // 32: j = lane
    int lane = threadIdx.x & 31;
    int c0 = lane * 4;
    const float invN = 1.0f / NN;
    float4 sc4, sh4;
    {
        float m0 = g_sum[slot][c0 + 0] * invN, m1 = g_sum[slot][c0 + 1] * invN;
        float m2 = g_sum[slot][c0 + 2] * invN, m3 = g_sum[slot][c0 + 3] * invN;
        float v0 = g_sumsq[slot][c0 + 0] * invN - m0 * m0;
        float v1 = g_sumsq[slot][c0 + 1] * invN - m1 * m1;
        float v2 = g_sumsq[slot][c0 + 2] * invN - m2 * m2;
        float v3 = g_sumsq[slot][c0 + 3] * invN - m3 * m3;
        sc4.x = gamma[c0 + 0] * rsqrtf(v0 + BN_EPS);
        sc4.y = gamma[c0 + 1] * rsqrtf(v1 + BN_EPS);
        sc4.z = gamma[c0 + 2] * rsqrtf(v2 + BN_EPS);
        sc4.w = gamma[c0 + 3] * rsqrtf(v3 + BN_EPS);
        sh4.x = beta[c0 + 0] - m0 * sc4.x;
        sh4.y = beta[c0 + 1] - m1 * sc4.y;
        sh4.z = beta[c0 + 2] - m2 * sc4.z;
        sh4.w = beta[c0 + 3] - m3 * sc4.w;
    }
    auto bnr = [&](float4 v) {
        v.x = fmaxf(v.x * sc4.x + sh4.x, 0.f);
        v.y = fmaxf(v.y * sc4.y + sh4.y, 0.f);
        v.z = fmaxf(v.z * sc4.z + sh4.z, 0.f);
        v.w = fmaxf(v.w * sc4.w + sh4.w, 0.f);
        return v;
    };

    int wstride = gridDim.x * 8;
    for (int cc = blockIdx.x * 8 + (threadIdx.x >> 5); cc < NCHUNK; cc += wstride) {
        int n0 = cc * BNP_CH;
        int curg = gids[n0];
        float4 pacc = make_float4(0.f, 0.f, 0.f, 0.f);
        for (int i = 0; i < BNP_CH; i++) {
            int node = n0 + i;
            int gcur = gids[node];
            if (gcur != curg) {
                atomicAdd(&out[(size_t)curg * OUTW + offprev + c0 + 0], pacc.x);
                atomicAdd(&out[(size_t)curg * OUTW + offprev + c0 + 1], pacc.y);
                atomicAdd(&out[(size_t)curg * OUTW + offprev + c0 + 2], pacc.z);
                atomicAdd(&out[(size_t)curg * OUTW + offprev + c0 + 3], pacc.w);
                pacc = make_float4(0.f, 0.f, 0.f, 0.f);
                curg = gcur;
            }
            // self h value (also pooled)
            float4 hv = bnr(((const float4*)rep)[(size_t)node * D4 + lane]);
            pacc.x += hv.x; pacc.y += hv.y; pacc.z += hv.z; pacc.w += hv.w;
            float4 acc = make_float4(hv.x * se, hv.y * se, hv.z * se, hv.w * se);

            int e0 = g_rowptr[node], e1 = g_rowptr[node + 1];
            int e = e0;
            for (; e + 4 <= e1; e += 4) {
                float4 v0 = bnr(((const float4*)rep)[(size_t)g_colidx[e] * D4 + lane]);
                float4 v1 = bnr(((const float4*)rep)[(size_t)g_colidx[e + 1] * D4 + lane]);
                float4 v2 = bnr(((const float4*)rep)[(size_t)g_colidx[e + 2] * D4 + lane]);
                float4 v3 = bnr(((const float4*)rep)[(size_t)g_colidx[e + 3] * D4 + lane]);
                acc.x += (v0.x + v1.x) + (v2.x + v3.x);
                acc.y += (v0.y + v1.y) + (v2.y + v3.y);
                acc.z += (v0.z + v1.z) + (v2.z + v3.z);
                acc.w += (v0.w + v1.w) + (v2.w + v3.w);
            }
            for (; e < e1; e++) {
                float4 v = bnr(((const float4*)rep)[(size_t)g_colidx[e] * D4 + lane]);
                acc.x += v.x; acc.y += v.y; acc.z += v.z; acc.w += v.w;
            }
            float r0, r1, r2, r3;
            uint32_t h01 = pack_f16(acc.x, acc.y, r0, r1);
            uint32_t h23 = pack_f16(acc.z, acc.w, r2, r3);
            pout[(size_t)node * D4 + lane] =
                make_uint4(h01, h23, pack_f16_rn(r0, r1), pack_f16_rn(r2, r3));
        }
        atomicAdd(&out[(size_t)curg * OUTW + offprev + c0 + 0], pacc.x);
        atomicAdd(&out[(size_t)curg * OUTW + offprev + c0 + 1], pacc.y);
        atomicAdd(&out[(size_t)curg * OUTW + offprev + c0 + 2], pacc.z);
        atomicAdd(&out[(size_t)curg * OUTW + offprev + c0 + 3], pacc.w);
    }
}

// GEMM phase: 64-row tiles strided by block; 2-term fp16 split.
template <int PACKED>
__device__ void gemm_phase(GemmSmem& sm,
                           const float* __restrict__ A, const uint4* __restrict__ Apk,
                           const uint32_t* __restrict__ wpk,
                           const float* __restrict__ bias, float* __restrict__ C, int K,
                           const float* __restrict__ bnga, const float* __restrict__ bnbe,
                           const float* __restrict__ psum, const float* __restrict__ psq,
                           float* __restrict__ osum, float* __restrict__ osumsq) {
    const int tid  = threadIdx.x;
    const int lane = tid & 31;
    const int wid  = tid >> 5;
    const int wr   = wid >> 2;
    const int wc   = wid & 3;
    const int gid  = lane >> 2;
    const int tq   = lane & 3;
    const int arA = tid & 63;
    const int kgA = tid >> 6;
    const int arW = tid & 127;
    const int kgW = tid >> 7;
    const int KP  = K >> 1;
    const int KP4 = K >> 2;
    const int T   = (K + 15) >> 4;

    if (!PACKED) {
        if (tid < DHF) {
            const float invN = 1.0f / NN;
            float m = psum[tid] * invN;
            float v = psq[tid] * invN - m * m;
            float sc = bnga[tid] * rsqrtf(v + BN_EPS);
            sm.strs[tid] = sc;
            sm.strh[tid] = bnbe[tid] - m * sc;
        }
        __syncthreads();
    }

    for (int tile = blockIdx.x; tile < NTILES; tile += gridDim.x) {
        const int row0 = tile * 64;
        const int grA  = row0 + arA;
        const bool rokA = (grA < NN);

        float acc[2][4][4];
#pragma unroll
        for (int mt = 0; mt < 2; mt++)
#pragma unroll
            for (int nt = 0; nt < 4; nt++)
#pragma unroll
                for (int j = 0; j < 4; j++) acc[mt][nt][j] = 0.f;

        float4 va;
        uint4 pa;
        uint32_t wk[4];

        auto prefetch = [&](int t) {
            if (PACKED) {
                int gp = t * 4 + kgA;
                pa = make_uint4(0u, 0u, 0u, 0u);
                if (rokA && gp < KP4) pa = Apk[(size_t)grA * KP4 + gp];
            } else {
                int gk0 = t * 16 + 4 * kgA;
                va = make_float4(0.f, 0.f, 0.f, 0.f);
                if (rokA && gk0 < K) va = *(const float4*)&A[(size_t)grA * K + gk0];
            }
#pragma unroll
            for (int j = 0; j < 4; j++) {
                int kp = t * 8 + kgW + 2 * j;
                wk[j] = (kp < KP) ? wpk[kp * DHF + arW] : 0u;
            }
        };

        auto stage = [&](int d, int k0) {
            if (PACKED) {
                sm.ash[d][2 * kgA][arA]     = pa.x;
                sm.ash[d][2 * kgA + 1][arA] = pa.y;
                sm.asl[d][2 * kgA][arA]     = pa.z;
                sm.asl[d][2 * kgA + 1][arA] = pa.w;
            } else {
                float a4[4] = {va.x, va.y, va.z, va.w};
                if (rokA) {
#pragma unroll
                    for (int j = 0; j < 4; j++) {
                        int gk = k0 + 4 * kgA + j;
                        a4[j] = (gk < K) ? fmaxf(a4[j] * sm.strs[gk] + sm.strh[gk], 0.f) : 0.f;
                    }
                }
#pragma unroll
                for (int p = 0; p < 2; p++) {
                    float r0f, r1f;
                    sm.ash[d][2 * kgA + p][arA] = pack_f16(a4[2 * p], a4[2 * p + 1], r0f, r1f);
                    sm.asl[d][2 * kgA + p][arA] = pack_f16_rn(r0f, r1f);
                }
            }
#pragma unroll
            for (int j = 0; j < 4; j++)
                sm.wsh[d][kgW + 2 * j][arW] = wk[j];
        };

        prefetch(0);
        stage(0, 0);
        __syncthreads();

        for (int t = 0; t < T; t++) {
            const int cur = t & 1;
            if (t + 1 < T) prefetch(t + 1);
            {
                uint32_t bh[4][2];
#pragma unroll
                for (int nt = 0; nt < 4; nt++) {
                    int col = wc * 32 + nt * 8 + gid;
                    bh[nt][0] = sm.wsh[cur][tq][col];
                    bh[nt][1] = sm.wsh[cur][tq + 4][col];
                }
#pragma unroll
                for (int mt = 0; mt < 2; mt++) {
                    int r0 = wr * 32 + mt * 16;
                    uint32_t ah[4], al[4];
                    ah[0] = sm.ash[cur][tq][r0 + gid];
                    ah[1] = sm.ash[cur][tq][r0 + gid + 8];
                    ah[2] = sm.ash[cur][tq + 4][r0 + gid];
                    ah[3] = sm.ash[cur][tq + 4][r0 + gid + 8];
                    al[0] = sm.asl[cur][tq][r0 + gid];
                    al[1] = sm.asl[cur][tq][r0 + gid + 8];
                    al[2] = sm.asl[cur][tq + 4][r0 + gid];
                    al[3] = sm.asl[cur][tq + 4][r0 + gid + 8];
#pragma unroll
                    for (int nt = 0; nt < 4; nt++) {
                        mma16(acc[mt][nt], ah, bh[nt]);   // hiA * W
                        mma16(acc[mt][nt], al, bh[nt]);   // loA * W
                    }
                }
            }
            if (t + 1 < T) stage((t + 1) & 1, (t + 1) * 16);
            __syncthreads();
        }

        // epilogue: bias, store, column stats
        float cs[4][2], cq[4][2];
#pragma unroll
        for (int nt = 0; nt < 4; nt++)
#pragma unroll
            for (int j = 0; j < 2; j++) { cs[nt][j] = 0.f; cq[nt][j] = 0.f; }

#pragma unroll
        for (int mt = 0; mt < 2; mt++) {
            int rbase = row0 + wr * 32 + mt * 16;
#pragma unroll
            for (int nt = 0; nt < 4; nt++) {
                int colb = wc * 32 + nt * 8 + 2 * tq;
                float b0 = bias[colb], b1 = bias[colb + 1];
                int r1 = rbase + gid;
                int r2 = rbase + gid + 8;
                if (r1 < NN) {
                    float v0 = acc[mt][nt][0] + b0;
                    float v1 = acc[mt][nt][1] + b1;
                    *(float2*)&C[(size_t)r1 * 128 + colb] = make_float2(v0, v1);
                    cs[nt][0] += v0; cq[nt][0] += v0 * v0;
                    cs[nt][1] += v1; cq[nt][1] += v1 * v1;
                }
                if (r2 < NN) {
                    float v0 = acc[mt][nt][2] + b0;
                    float v1 = acc[mt][nt][3] + b1;
                    *(float2*)&C[(size_t)r2 * 128 + colb] = make_float2(v0, v1);
                    cs[nt][0] += v0; cq[nt][0] += v0 * v0;
                    cs[nt][1] += v1; cq[nt][1] += v1 * v1;
                }
            }
        }
#pragma unroll
        for (int nt = 0; nt < 4; nt++)
#pragma unroll
            for (int j = 0; j < 2; j++) {
                float s = cs[nt][j], q = cq[nt][j];
                s += __shfl_xor_sync(0xffffffffu, s, 4);
                s += __shfl_xor_sync(0xffffffffu, s, 8);
                s += __shfl_xor_sync(0xffffffffu, s, 16);
                q += __shfl_xor_sync(0xffffffffu, q, 4);
                q += __shfl_xor_sync(0xffffffffu, q, 8);
                q += __shfl_xor_sync(0xffffffffu, q, 16);
                if (gid == 0) {
                    int col = wc * 32 + nt * 8 + 2 * tq + j;
                    atomicAdd(&osum[col], s);
                    atomicAdd(&osumsq[col], q);
                }
            }
        __syncthreads();
    }
}

// final-layer BN+ReLU+pool (no h write)
__device__ void bnpool_phase(const float* __restrict__ rep,
                             float* __restrict__ out, int off,
                             const float* __restrict__ gamma, const float* __restrict__ beta,
                             const int* __restrict__ gids, int slot) {
    int c = threadIdx.x & 127;
    int half = threadIdx.x >> 7;
    const float invN = 1.0f / NN;
    float m = g_sum[slot][c] * invN;
    float v = g_sumsq[slot][c] * invN - m * m;
    float sc = gamma[c] * rsqrtf(v + BN_EPS);
    float sh = beta[c] - m * sc;

    for (int cc = blockIdx.x * 2 + half; cc < NCHUNK; cc += gridDim.x * 2) {
        int r0 = cc * BNP_CH;
        float vals[BNP_CH];
        int gv[BNP_CH];
#pragma unroll
        for (int i = 0; i < BNP_CH; i++) {
            vals[i] = rep[(size_t)(r0 + i) * DHF + c];
            gv[i] = gids[r0 + i];
        }
#pragma unroll
        for (int i = 0; i < BNP_CH; i++)
            vals[i] = fmaxf(vals[i] * sc + sh, 0.f);
        int curg = gv[0];
        float acc = 0.f;
#pragma unroll
        for (int i = 0; i < BNP_CH; i++) {
            if (gv[i] != curg) {
                atomicAdd(&out[(size_t)curg * OUTW + off + c], acc);
                acc = 0.f;
                curg = gv[i];
            }
            acc += vals[i];
        }
        atomicAdd(&out[(size_t)curg * OUTW + off + c], acc);
    }
}

// raw-x pooling (layer 0 only), 16-row chunks strided
__device__ void poolx_phase(const float* __restrict__ src, float* __restrict__ out,
                            const int* __restrict__ gids) {
    int c = threadIdx.x;
    if (c >= DINF) return;
    for (int cc = blockIdx.x; cc < NCHUNK; cc += gridDim.x) {
        int r0 = cc * BNP_CH;
        float vals[BNP_CH];
        int gv[BNP_CH];
#pragma unroll
        for (int i = 0; i < BNP_CH; i++) {
            vals[i] = src[(size_t)(r0 + i) * DINF + c];
            gv[i] = gids[r0 + i];
        }
        int curg = gv[0];
        float acc = 0.f;
#pragma unroll
        for (int i = 0; i < BNP_CH; i++) {
            if (gv[i] != curg) {
                atomicAdd(&out[(size_t)curg * OUTW + c], acc);
                acc = 0.f;
                curg = gv[i];
            }
            acc += vals[i];
        }
        atomicAdd(&out[(size_t)curg * OUTW + c], acc);
    }
}

// ---------------- fused layer kernel ----------------------------------------
// li==0: spmm(x) + poolx; li>=1: spmm reads raw rep with fused BN+ReLU and
// pools previous layer's h. Final layer also runs bnpool for its own output.
__global__ __launch_bounds__(256, 3)
void k_layer(const float* __restrict__ xraw, const float* __restrict__ epsv, int li, int K1,
             const uint32_t* __restrict__ wpk1, const float* __restrict__ b1,
             const uint32_t* __restrict__ wpk2, const float* __restrict__ b2,
             const float* __restrict__ ga, const float* __restrict__ bea,
             const float* __restrict__ gprev, const float* __restrict__ bprev,
             const float* __restrict__ gb, const float* __restrict__ bbb,
             const int* __restrict__ gids, float* __restrict__ out) {
    __shared__ GemmSmem gsm;
    float se = 1.0f + epsv[li];

    // phase A
    if (li == 0) {
        spmm_x_phase(xraw, g_apk, se);
        poolx_phase(xraw, out, gids);
    } else {
        spmm_bnpool_phase(g_rep, g_apk, se, 2 * li - 1, gprev, bprev,
                          gids, out, DINF + (li - 1) * DHF);
    }
    grid_sync();

    // phase B: GEMM1 (packed A) -> mid + stats[2l]
    gemm_phase<1>(gsm, nullptr, g_apk, wpk1, b1, g_mid, K1,
                  nullptr, nullptr, nullptr, nullptr,
                  g_sum[2 * li], g_sumsq[2 * li]);
    grid_sync();

    // phase C: BN-fold + GEMM2 (fp32 A=mid) -> rep + stats[2l+1]
    gemm_phase<0>(gsm, g_mid, nullptr, wpk2, b2, g_rep, DHF,
                  ga, bea, g_sum[2 * li], g_sumsq[2 * li],
                  g_sum[2 * li + 1], g_sumsq[2 * li + 1]);

    // final layer: its own BN+ReLU+pool
    if (li == NLAY - 1) {
        grid_sync();
        bnpool_phase(g_rep, out, DINF + li * DHF, gb, bbb, gids, 2 * li + 1);
    }
}

// ---------------- launch ---------------------------------------------------
extern "C" void kernel_launch(void* const* d_in, const int* in_sizes, int n_in,
                              void* d_out, int out_size) {
    const float* x     = (const float*)d_in[0];
    const int*   erow  = (const int*)d_in[1];
    const int*   ecol  = (const int*)d_in[2];
    const int*   gid   = (const int*)d_in[3];
    const float* eps   = (const float*)d_in[4];
    const float* w1_0  = (const float*)d_in[5];
    const float* b1_0  = (const float*)d_in[6];
    const float* g1_0  = (const float*)d_in[7];
    const float* be1_0 = (const float*)d_in[8];
    const float* w2_0  = (const float*)d_in[9];
    const float* b2_0  = (const float*)d_in[10];
    const float* gbn_0 = (const float*)d_in[11];
    const float* bbn_0 = (const float*)d_in[12];
    const float* w1_r  = (const float*)d_in[13];
    const float* b1_r  = (const float*)d_in[14];
    const float* g1_r  = (const float*)d_in[15];
    const float* be1_r = (const float*)d_in[16];
    const float* w2_r  = (const float*)d_in[17];
    const float* b2_r  = (const float*)d_in[18];
    const float* gbn_r = (const float*)d_in[19];
    const float* bbn_r = (const float*)d_in[20];
    float* out = (float*)d_out;

    int E = in_sizes[1];

    uint32_t *wpk;
    cudaGetSymbolAddress((void**)&wpk, g_wpk);

    const int scan_smem = (NN + 1024) * (int)sizeof(int);
    cudaFuncSetAttribute(k_scan_big, cudaFuncAttributeMaxDynamicSharedMemorySize, scan_smem);

    int dev = 0;
    cudaGetDevice(&dev);
    int nsm = 0;
    cudaDeviceGetAttribute(&nsm, cudaDevAttrMultiProcessorCount, dev);
    int occ = 0;
    cudaOccupancyMaxActiveBlocksPerMultiprocessor(&occ, k_layer, 256, 0);
    if (occ < 1) occ = 1;
    const int lgrid = nsm * occ;

    k_packw<<<WPAIRS, DHF>>>(w1_0, w2_0, w1_r, w2_r, out, out_size);
    k_hist<<<(E + 255) / 256, 256>>>(erow, E);
    k_scan_big<<<1, 1024, scan_smem>>>();
    k_scatter<<<(E + 255) / 256, 256>>>(erow, ecol, E);

    const int woff_g1[NLAY] = {0, 164, 228, 292};
    const int woff_g2[NLAY] = {100, 356, 420, 484};

    for (int l = 0; l < NLAY; l++) {
        const float *ba, *ga, *bea, *bb, *gb, *bbb, *gprev, *bprev;
        int K1;
        if (l == 0) {
            K1 = DINF;
            ba = b1_0; ga = g1_0; bea = be1_0;
            bb = b2_0; gb = gbn_0; bbb = bbn_0;
            gprev = nullptr; bprev = nullptr;
        } else {
            K1 = DHF;
            int o1 = (l - 1) * DHF;
            ba = b1_r + o1; ga = g1_r + o1; bea = be1_r + o1;
            bb = b2_r + o1; gb = gbn_r + o1; bbb = bbn_r + o1;
            gprev = (l == 1) ? gbn_0 : gbn_r + (l - 2) * DHF;
            bprev = (l == 1) ? bbn_0 : bbn_r + (l - 2) * DHF;
        }
        k_layer<<<lgrid, 256>>>(x, eps, l, K1,
                                wpk + woff_g1[l] * DHF, ba,
                                wpk + woff_g2[l] * DHF, bb,
                                ga, bea, gprev, bprev, gb, bbb,
                                gid, out);
    }
}

// round 17
// speedup vs baseline: 1.0099x; 1.0099x over previous
#include <cuda_runtime.h>
#include <cuda_fp16.h>
#include <cstdint>

// Problem constants (fixed-shape problem)
#define NN      50000
#define EE_MAX  800000
#define GG      128
#define DINF    200
#define DHF     128
#define NLAY    4
#define BN_EPS  1e-5f
#define OUTW    (DINF + NLAY * DHF)   // 712
#define WPAIRS  548
#define APK_W   50
#define NTILES  ((NN + 63) / 64)      // 782
#define BNP_CH  16
#define NCHUNK  (NN / BNP_CH)         // 3125 exact
#define SCAN_B  196                   // scan blocks (196*256 >= NN)

// ---------------- scratch (device globals; no allocation allowed) ----------
__device__ uint4    g_apk    [NN * APK_W];
__device__ float    g_mid    [NN * DHF];
__device__ float    g_rep    [NN * DHF];
__device__ float    g_h      [NN * DHF];
__device__ int      g_cnt    [2 * NN];
__device__ int      g_rowptr [NN + 1];
__device__ int      g_colidx [EE_MAX];
__device__ int      g_bsum   [256];
__device__ float    g_sum    [2 * NLAY][DHF];
__device__ float    g_sumsq  [2 * NLAY][DHF];
__device__ uint32_t g_wpk    [WPAIRS * DHF];
__device__ unsigned g_bar_cnt;
__device__ unsigned g_bar_gen;

// ---------------- device-wide barrier (all blocks resident) ----------------
__device__ __forceinline__ void grid_sync() {
    __syncthreads();
    if (threadIdx.x == 0) {
        unsigned gen = *(volatile unsigned*)&g_bar_gen;
        __threadfence();
        unsigned ticket = atomicAdd(&g_bar_cnt, 1u);
        if (ticket == gridDim.x - 1) {
            g_bar_cnt = 0u;
            __threadfence();
            atomicAdd(&g_bar_gen, 1u);
        } else {
            while (*(volatile unsigned*)&g_bar_gen == gen) __nanosleep(64);
        }
        __threadfence();
    }
    __syncthreads();
}

// ---------------- fp16 hi/lo split helpers ---------------------------------
__device__ __forceinline__ uint32_t pack_f16(float v0, float v1, float& rem0, float& rem1) {
    __half h0 = __float2half_rn(v0);
    __half h1 = __float2half_rn(v1);
    rem0 = v0 - __half2float(h0);
    rem1 = v1 - __half2float(h1);
    return ((uint32_t)__half_as_ushort(h1) << 16) | (uint32_t)__half_as_ushort(h0);
}
__device__ __forceinline__ uint32_t pack_f16_rn(float v0, float v1) {
    __half2 p = __floats2half2_rn(v0, v1);   // .x = v0 (low half)
    return *(uint32_t*)&p;
}

__device__ __forceinline__ void mma16(float* c, const uint32_t* a, const uint32_t* b) {
    asm volatile(
        "mma.sync.aligned.m16n8k16.row.col.f32.f16.f16.f32 "
        "{%0,%1,%2,%3}, {%4,%5,%6,%7}, {%8,%9}, {%0,%1,%2,%3};"
        : "+f"(c[0]), "+f"(c[1]), "+f"(c[2]), "+f"(c[3])
        : "r"(a[0]), "r"(a[1]), "r"(a[2]), "r"(a[3]), "r"(b[0]), "r"(b[1]));
}

struct GemmSmem {
    uint32_t ash[2][8][72], asl[2][8][72];
    uint32_t wsh[2][8][136];
    float strs[DHF], strh[DHF];
};

// ---------------- prep phase: wpk pack + zero cnt/out/stats -----------------
__device__ void prep_phase(const float* __restrict__ w1_0, const float* __restrict__ w2_0,
                           const float* __restrict__ w1_r, const float* __restrict__ w2_r,
                           float* __restrict__ out, int out_n) {
    int gt = blockIdx.x * blockDim.x + threadIdx.x;
    int gs = gridDim.x * blockDim.x;
    for (int i = gt; i < NN; i += gs) g_cnt[i] = 0;
    for (int i = gt; i < out_n; i += gs) out[i] = 0.f;
    for (int i = gt; i < 2 * NLAY * DHF; i += gs) {
        ((float*)g_sum)[i] = 0.f;
        ((float*)g_sumsq)[i] = 0.f;
    }
    for (int i = gt; i < WPAIRS * DHF; i += gs) {
        int b = i >> 7, c = i & 127;
        const float* src;
        int kp;
        if (b < 100)      { src = w1_0; kp = b; }
        else if (b < 164) { src = w2_0; kp = b - 100; }
        else {
            int r = b - 164;
            if (r < 192) { src = w1_r + (r / 64) * DHF * DHF; kp = r % 64; }
            else { r -= 192; src = w2_r + (r / 64) * DHF * DHF; kp = r % 64; }
        }
        float v0 = src[(size_t)(2 * kp) * DHF + c];
        float v1 = src[(size_t)(2 * kp + 1) * DHF + c];
        g_wpk[i] = pack_f16_rn(v0, v1);
    }
}

// ---------------- CSR phases -------------------------------------------------
__device__ void hist_phase(const int* __restrict__ erow, int E) {
    int gt = blockIdx.x * blockDim.x + threadIdx.x;
    int gs = gridDim.x * blockDim.x;
    for (int e = gt; e < E; e += gs) atomicAdd(&g_cnt[erow[e]], 1);
}

__device__ void scan_a_phase() {
    __shared__ int ss[256];
    int gt = blockIdx.x * blockDim.x + threadIdx.x;
    int gs = gridDim.x * blockDim.x;
    for (int i = gt; i < NN; i += gs) g_cnt[NN + i] = 0;   // scatter cursors

    int b = blockIdx.x;
    if (b >= SCAN_B) return;
    int t = threadIdx.x;
    int i = b * 256 + t;
    int v = (i < NN) ? g_cnt[i] : 0;
    ss[t] = v;
    __syncthreads();
#pragma unroll
    for (int off = 1; off < 256; off <<= 1) {
        int u = (t >= off) ? ss[t - off] : 0;
        __syncthreads();
        ss[t] += u;
        __syncthreads();
    }
    if (i < NN) g_rowptr[i] = ss[t] - v;   // block-local exclusive
    if (t == 255) g_bsum[b] = ss[255];
}

__device__ void scan_b_phase() {
    if (blockIdx.x != 0) return;
    __shared__ int sb[256];
    int t = threadIdx.x;
    int v = (t < SCAN_B) ? g_bsum[t] : 0;
    sb[t] = v;
    __syncthreads();
#pragma unroll
    for (int off = 1; off < 256; off <<= 1) {
        int u = (t >= off) ? sb[t - off] : 0;
        __syncthreads();
        sb[t] += u;
        __syncthreads();
    }
    if (t < SCAN_B) g_bsum[t] = sb[t] - v;     // exclusive block offsets
    if (t == SCAN_B - 1) g_rowptr[NN] = sb[t]; // total
}

__device__ void scan_c_phase() {
    int b = blockIdx.x;
    if (b >= SCAN_B) return;
    int i = b * 256 + threadIdx.x;
    if (i < NN) g_rowptr[i] += g_bsum[b];
}

__device__ void scatter_phase(const int* __restrict__ erow, const int* __restrict__ ecol, int E) {
    int gt = blockIdx.x * blockDim.x + threadIdx.x;
    int gs = gridDim.x * blockDim.x;
    for (int e = gt; e < E; e += gs) {
        int r = erow[e];
        int p = g_rowptr[r] + atomicAdd(&g_cnt[NN + r], 1);
        g_colidx[p] = ecol[e];
    }
}

// ---------------- spmm phase (warp per node, strided) ------------------------
template <int D4>
__device__ void spmm_phase(const float* __restrict__ hin, uint4* __restrict__ pout,
                           float se) {
    const int S = (D4 + 31) / 32;
    int lane = threadIdx.x & 31;
    int wstride = gridDim.x * 8;
    for (int wid = blockIdx.x * 8 + (threadIdx.x >> 5); wid < NN; wid += wstride) {
        const float4* selfr = (const float4*)hin + (size_t)wid * D4;
        float4 acc[S];
#pragma unroll
        for (int s = 0; s < S; s++) {
            int j = lane + 32 * s;
            if (j < D4) {
                float4 v = selfr[j];
                acc[s] = make_float4(v.x * se, v.y * se, v.z * se, v.w * se);
            } else acc[s] = make_float4(0.f, 0.f, 0.f, 0.f);
        }
        int e0 = g_rowptr[wid], e1 = g_rowptr[wid + 1];
        int e = e0;
        for (; e + 4 <= e1; e += 4) {
            const float4* r0 = (const float4*)hin + (size_t)g_colidx[e] * D4;
            const float4* r1 = (const float4*)hin + (size_t)g_colidx[e + 1] * D4;
            const float4* r2 = (const float4*)hin + (size_t)g_colidx[e + 2] * D4;
            const float4* r3 = (const float4*)hin + (size_t)g_colidx[e + 3] * D4;
#pragma unroll
            for (int s = 0; s < S; s++) {
                int j = lane + 32 * s;
                if (j < D4) {
                    float4 v0 = r0[j], v1 = r1[j], v2 = r2[j], v3 = r3[j];
                    acc[s].x += (v0.x + v1.x) + (v2.x + v3.x);
                    acc[s].y += (v0.y + v1.y) + (v2.y + v3.y);
                    acc[s].z += (v0.z + v1.z) + (v2.z + v3.z);
                    acc[s].w += (v0.w + v1.w) + (v2.w + v3.w);
                }
            }
        }
        for (; e < e1; e++) {
            const float4* r = (const float4*)hin + (size_t)g_colidx[e] * D4;
#pragma unroll
            for (int s = 0; s < S; s++) {
                int j = lane + 32 * s;
                if (j < D4) {
                    float4 v = r[j];
                    acc[s].x += v.x; acc[s].y += v.y; acc[s].z += v.z; acc[s].w += v.w;
                }
            }
        }
        uint4* o = pout + (size_t)wid * D4;
#pragma unroll
        for (int s = 0; s < S; s++) {
            int j = lane + 32 * s;
            if (j < D4) {
                float r0, r1, r2, r3;
                uint32_t h01 = pack_f16(acc[s].x, acc[s].y, r0, r1);
                uint32_t h23 = pack_f16(acc[s].z, acc[s].w, r2, r3);
                o[j] = make_uint4(h01, h23, pack_f16_rn(r0, r1), pack_f16_rn(r2, r3));
            }
        }
    }
}

// ---------------- GEMM phase (64-row tiles, 2-term fp16 split) ---------------
template <int PACKED>
__device__ void gemm_phase(GemmSmem& sm,
                           const float* __restrict__ A, const uint4* __restrict__ Apk,
                           const uint32_t* __restrict__ wpk,
                           const float* __restrict__ bias, float* __restrict__ C, int K,
                           const float* __restrict__ bnga, const float* __restrict__ bnbe,
                           const float* __restrict__ psum, const float* __restrict__ psq,
                           float* __restrict__ osum, float* __restrict__ osumsq) {
    const int tid  = threadIdx.x;
    const int lane = tid & 31;
    const int wid  = tid >> 5;
    const int wr   = wid >> 2;
    const int wc   = wid & 3;
    const int gid  = lane >> 2;
    const int tq   = lane & 3;
    const int arA = tid & 63;
    const int kgA = tid >> 6;
    const int arW = tid & 127;
    const int kgW = tid >> 7;
    const int KP  = K >> 1;
    const int KP4 = K >> 2;
    const int T   = (K + 15) >> 4;

    if (!PACKED) {
        if (tid < DHF) {
            const float invN = 1.0f / NN;
            float m = psum[tid] * invN;
            float v = psq[tid] * invN - m * m;
            float sc = bnga[tid] * rsqrtf(v + BN_EPS);
            sm.strs[tid] = sc;
            sm.strh[tid] = bnbe[tid] - m * sc;
        }
        __syncthreads();
    }

    for (int tile = blockIdx.x; tile < NTILES; tile += gridDim.x) {
        const int row0 = tile * 64;
        const int grA  = row0 + arA;
        const bool rokA = (grA < NN);

        float acc[2][4][4];
#pragma unroll
        for (int mt = 0; mt < 2; mt++)
#pragma unroll
            for (int nt = 0; nt < 4; nt++)
#pragma unroll
                for (int j = 0; j < 4; j++) acc[mt][nt][j] = 0.f;

        float4 va;
        uint4 pa;
        uint32_t wk[4];

        auto prefetch = [&](int t) {
            if (PACKED) {
                int gp = t * 4 + kgA;
                pa = make_uint4(0u, 0u, 0u, 0u);
                if (rokA && gp < KP4) pa = Apk[(size_t)grA * KP4 + gp];
            } else {
                int gk0 = t * 16 + 4 * kgA;
                va = make_float4(0.f, 0.f, 0.f, 0.f);
                if (rokA && gk0 < K) va = *(const float4*)&A[(size_t)grA * K + gk0];
            }
#pragma unroll
            for (int j = 0; j < 4; j++) {
                int kp = t * 8 + kgW + 2 * j;
                wk[j] = (kp < KP) ? wpk[kp * DHF + arW] : 0u;
            }
        };

        auto stage = [&](int d, int k0) {
            if (PACKED) {
                sm.ash[d][2 * kgA][arA]     = pa.x;
                sm.ash[d][2 * kgA + 1][arA] = pa.y;
                sm.asl[d][2 * kgA][arA]     = pa.z;
                sm.asl[d][2 * kgA + 1][arA] = pa.w;
            } else {
                float a4[4] = {va.x, va.y, va.z, va.w};
                if (rokA) {
#pragma unroll
                    for (int j = 0; j < 4; j++) {
                        int gk = k0 + 4 * kgA + j;
                        a4[j] = (gk < K) ? fmaxf(a4[j] * sm.strs[gk] + sm.strh[gk], 0.f) : 0.f;
                    }
                }
#pragma unroll
                for (int p = 0; p < 2; p++) {
                    float r0f, r1f;
                    sm.ash[d][2 * kgA + p][arA] = pack_f16(a4[2 * p], a4[2 * p + 1], r0f, r1f);
                    sm.asl[d][2 * kgA + p][arA] = pack_f16_rn(r0f, r1f);
                }
            }
#pragma unroll
            for (int j = 0; j < 4; j++)
                sm.wsh[d][kgW + 2 * j][arW] = wk[j];
        };

        prefetch(0);
        stage(0, 0);
        __syncthreads();

        for (int t = 0; t < T; t++) {
            const int cur = t & 1;
            if (t + 1 < T) prefetch(t + 1);
            {
                uint32_t bh[4][2];
#pragma unroll
                for (int nt = 0; nt < 4; nt++) {
                    int col = wc * 32 + nt * 8 + gid;
                    bh[nt][0] = sm.wsh[cur][tq][col];
                    bh[nt][1] = sm.wsh[cur][tq + 4][col];
                }
#pragma unroll
                for (int mt = 0; mt < 2; mt++) {
                    int r0 = wr * 32 + mt * 16;
                    uint32_t ah[4], al[4];
                    ah[0] = sm.ash[cur][tq][r0 + gid];
                    ah[1] = sm.ash[cur][tq][r0 + gid + 8];
                    ah[2] = sm.ash[cur][tq + 4][r0 + gid];
                    ah[3] = sm.ash[cur][tq + 4][r0 + gid + 8];
                    al[0] = sm.asl[cur][tq][r0 + gid];
                    al[1] = sm.asl[cur][tq][r0 + gid + 8];
                    al[2] = sm.asl[cur][tq + 4][r0 + gid];
                    al[3] = sm.asl[cur][tq + 4][r0 + gid + 8];
#pragma unroll
                    for (int nt = 0; nt < 4; nt++) {
                        mma16(acc[mt][nt], ah, bh[nt]);   // hiA * W
                        mma16(acc[mt][nt], al, bh[nt]);   // loA * W
                    }
                }
            }
            if (t + 1 < T) stage((t + 1) & 1, (t + 1) * 16);
            __syncthreads();
        }

        // epilogue: bias, store, column stats
        float cs[4][2], cq[4][2];
#pragma unroll
        for (int nt = 0; nt < 4; nt++)
#pragma unroll
            for (int j = 0; j < 2; j++) { cs[nt][j] = 0.f; cq[nt][j] = 0.f; }

#pragma unroll
        for (int mt = 0; mt < 2; mt++) {
            int rbase = row0 + wr * 32 + mt * 16;
#pragma unroll
            for (int nt = 0; nt < 4; nt++) {
                int colb = wc * 32 + nt * 8 + 2 * tq;
                float b0 = bias[colb], b1 = bias[colb + 1];
                int r1 = rbase + gid;
                int r2 = rbase + gid + 8;
                if (r1 < NN) {
                    float v0 = acc[mt][nt][0] + b0;
                    float v1 = acc[mt][nt][1] + b1;
                    *(float2*)&C[(size_t)r1 * 128 + colb] = make_float2(v0, v1);
                    cs[nt][0] += v0; cq[nt][0] += v0 * v0;
                    cs[nt][1] += v1; cq[nt][1] += v1 * v1;
                }
                if (r2 < NN) {
                    float v0 = acc[mt][nt][2] + b0;
                    float v1 = acc[mt][nt][3] + b1;
                    *(float2*)&C[(size_t)r2 * 128 + colb] = make_float2(v0, v1);
                    cs[nt][0] += v0; cq[nt][0] += v0 * v0;
                    cs[nt][1] += v1; cq[nt][1] += v1 * v1;
                }
            }
        }
#pragma unroll
        for (int nt = 0; nt < 4; nt++)
#pragma unroll
            for (int j = 0; j < 2; j++) {
                float s = cs[nt][j], q = cq[nt][j];
                s += __shfl_xor_sync(0xffffffffu, s, 4);
                s += __shfl_xor_sync(0xffffffffu, s, 8);
                s += __shfl_xor_sync(0xffffffffu, s, 16);
                q += __shfl_xor_sync(0xffffffffu, q, 4);
                q += __shfl_xor_sync(0xffffffffu, q, 8);
                q += __shfl_xor_sync(0xffffffffu, q, 16);
                if (gid == 0) {
                    int col = wc * 32 + nt * 8 + 2 * tq + j;
                    atomicAdd(&osum[col], s);
                    atomicAdd(&osumsq[col], q);
                }
            }
        __syncthreads();
    }
}

// ---------------- BN+ReLU+pool phase (register-batched) ----------------------
__device__ void bnpool_phase(const float* __restrict__ rep, float* __restrict__ h,
                             float* __restrict__ out, int off,
                             const float* __restrict__ gamma, const float* __restrict__ beta,
                             const int* __restrict__ gids, int slot, int write_h) {
    int c = threadIdx.x & 127;
    int half = threadIdx.x >> 7;
    const float invN = 1.0f / NN;
    float m = g_sum[slot][c] * invN;
    float v = g_sumsq[slot][c] * invN - m * m;
    float sc = gamma[c] * rsqrtf(v + BN_EPS);
    float sh = beta[c] - m * sc;

    for (int cc = blockIdx.x * 2 + half; cc < NCHUNK; cc += gridDim.x * 2) {
        int r0 = cc * BNP_CH;
        float vals[BNP_CH];
        int gv[BNP_CH];
#pragma unroll
        for (int i = 0; i < BNP_CH; i++) {
            vals[i] = rep[(size_t)(r0 + i) * DHF + c];
            gv[i] = gids[r0 + i];
        }
#pragma unroll
        for (int i = 0; i < BNP_CH; i++)
            vals[i] = fmaxf(vals[i] * sc + sh, 0.f);
        if (write_h) {
#pragma unroll
            for (int i = 0; i < BNP_CH; i++)
                h[(size_t)(r0 + i) * DHF + c] = vals[i];
        }
        int curg = gv[0];
        float acc = 0.f;
#pragma unroll
        for (int i = 0; i < BNP_CH; i++) {
            if (gv[i] != curg) {
                atomicAdd(&out[(size_t)curg * OUTW + off + c], acc);
                acc = 0.f;
                curg = gv[i];
            }
            acc += vals[i];
        }
        atomicAdd(&out[(size_t)curg * OUTW + off + c], acc);
    }
}

// raw-x pooling (layer 0 only)
__device__ void poolx_phase(const float* __restrict__ src, float* __restrict__ out,
                            const int* __restrict__ gids) {
    int c = threadIdx.x;
    if (c >= DINF) return;
    for (int cc = blockIdx.x; cc < NCHUNK; cc += gridDim.x) {
        int r0 = cc * BNP_CH;
        float vals[BNP_CH];
        int gv[BNP_CH];
#pragma unroll
        for (int i = 0; i < BNP_CH; i++) {
            vals[i] = src[(size_t)(r0 + i) * DINF + c];
            gv[i] = gids[r0 + i];
        }
        int curg = gv[0];
        float acc = 0.f;
#pragma unroll
        for (int i = 0; i < BNP_CH; i++) {
            if (gv[i] != curg) {
                atomicAdd(&out[(size_t)curg * OUTW + c], acc);
                acc = 0.f;
                curg = gv[i];
            }
            acc += vals[i];
        }
        atomicAdd(&out[(size_t)curg * OUTW + c], acc);
    }
}

// ---------------- mega kernel: whole network in one launch -------------------
__global__ __launch_bounds__(256, 3)
void k_mega(const float* __restrict__ x,
            const int* __restrict__ erow, const int* __restrict__ ecol,
            const int* __restrict__ gids, const float* __restrict__ epsv,
            const float* __restrict__ w1_0, const float* __restrict__ b1_0,
            const float* __restrict__ g1_0, const float* __restrict__ be1_0,
            const float* __restrict__ w2_0, const float* __restrict__ b2_0,
            const float* __restrict__ gbn_0, const float* __restrict__ bbn_0,
            const float* __restrict__ w1_r, const float* __restrict__ b1_r,
            const float* __restrict__ g1_r, const float* __restrict__ be1_r,
            const float* __restrict__ w2_r, const float* __restrict__ b2_r,
            const float* __restrict__ gbn_r, const float* __restrict__ bbn_r,
            float* __restrict__ out, int out_n, int E) {
    __shared__ GemmSmem gsm;

    // ---- prep + CSR build ----
    prep_phase(w1_0, w2_0, w1_r, w2_r, out, out_n);
    grid_sync();
    hist_phase(erow, E);
    grid_sync();
    scan_a_phase();
    grid_sync();
    scan_b_phase();
    grid_sync();
    scan_c_phase();
    grid_sync();
    scatter_phase(erow, ecol, E);
    grid_sync();

    const int woff_g1[NLAY] = {0, 164, 228, 292};
    const int woff_g2[NLAY] = {100, 356, 420, 484};

    for (int l = 0; l < NLAY; l++) {
        const float *ba, *ga, *bea, *bb, *gb, *bbb;
        int K1;
        if (l == 0) {
            K1 = DINF;
            ba = b1_0; ga = g1_0; bea = be1_0;
            bb = b2_0; gb = gbn_0; bbb = bbn_0;
        } else {
            K1 = DHF;
            int o1 = (l - 1) * DHF;
            ba = b1_r + o1; ga = g1_r + o1; bea = be1_r + o1;
            bb = b2_r + o1; gb = gbn_r + o1; bbb = bbn_r + o1;
        }
        const uint32_t* wpk1 = g_wpk + woff_g1[l] * DHF;
        const uint32_t* wpk2 = g_wpk + woff_g2[l] * DHF;
        float se = 1.0f + epsv[l];

        // phase A: spmm (+ poolx on layer 0)
        if (l == 0) {
            spmm_phase<DINF / 4>(x, g_apk, se);
            poolx_phase(x, out, gids);
        } else {
            spmm_phase<DHF / 4>(g_h, g_apk, se);
        }
        grid_sync();

        // phase B: GEMM1 (packed A) -> mid + stats[2l]
        gemm_phase<1>(gsm, nullptr, g_apk, wpk1, ba, g_mid, K1,
                      nullptr, nullptr, nullptr, nullptr,
                      g_sum[2 * l], g_sumsq[2 * l]);
        grid_sync();

        // phase C: BN-fold + GEMM2 (fp32 A=mid) -> rep + stats[2l+1]
        gemm_phase<0>(gsm, g_mid, nullptr, wpk2, bb, g_rep, DHF,
                      ga, bea, g_sum[2 * l], g_sumsq[2 * l],
                      g_sum[2 * l + 1], g_sumsq[2 * l + 1]);
        grid_sync();

        // phase D: BN + ReLU + pool (+ write h for layers 0..2)
        bnpool_phase(g_rep, g_h, out, DINF + l * DHF, gb, bbb, gids,
                     2 * l + 1, (l < NLAY - 1) ? 1 : 0);
        if (l < NLAY - 1) grid_sync();
    }
}

// ---------------- launch ---------------------------------------------------
extern "C" void kernel_launch(void* const* d_in, const int* in_sizes, int n_in,
                              void* d_out, int out_size) {
    const float* x     = (const float*)d_in[0];
    const int*   erow  = (const int*)d_in[1];
    const int*   ecol  = (const int*)d_in[2];
    const int*   gid   = (const int*)d_in[3];
    const float* eps   = (const float*)d_in[4];
    const float* w1_0  = (const float*)d_in[5];
    const float* b1_0  = (const float*)d_in[6];
    const float* g1_0  = (const float*)d_in[7];
    const float* be1_0 = (const float*)d_in[8];
    const float* w2_0  = (const float*)d_in[9];
    const float* b2_0  = (const float*)d_in[10];
    const float* gbn_0 = (const float*)d_in[11];
    const float* bbn_0 = (const float*)d_in[12];
    const float* w1_r  = (const float*)d_in[13];
    const float* b1_r  = (const float*)d_in[14];
    const float* g1_r  = (const float*)d_in[15];
    const float* be1_r = (const float*)d_in[16];
    const float* w2_r  = (const float*)d_in[17];
    const float* b2_r  = (const float*)d_in[18];
    const float* gbn_r = (const float*)d_in[19];
    const float* bbn_r = (const float*)d_in[20];
    float* out = (float*)d_out;

    int E = in_sizes[1];

    // resident-grid size: SMs x achievable occupancy (barrier safety)
    int dev = 0;
    cudaGetDevice(&dev);
    int nsm = 0;
    cudaDeviceGetAttribute(&nsm, cudaDevAttrMultiProcessorCount, dev);
    int occ = 0;
    cudaOccupancyMaxActiveBlocksPerMultiprocessor(&occ, k_mega, 256, 0);
    if (occ < 1) occ = 1;
    const int lgrid = nsm * occ;

    k_mega<<<lgrid, 256>>>(x, erow, ecol, gid, eps,
                           w1_0, b1_0, g1_0, be1_0, w2_0, b2_0, gbn_0, bbn_0,
                           w1_r, b1_r, g1_r, be1_r, w2_r, b2_r, gbn_r, bbn_r,
                           out, out_size, E);
}